// round 1
// baseline (speedup 1.0000x reference)
#include <cuda_runtime.h>
#include <math.h>

#define BB 16
#define CC 128
#define DD 32
#define NN 2048
#define NT 128

// ---------------- device scratch (static, no allocation) ----------------
__device__ float g_q[BB * DD * NN];      // 4 MB   q[b][d][n]
__device__ float g_v[BB * CC * NN];      // 16 MB  v[b][d][n]
__device__ float g_y[BB * CC * NN];      // 16 MB  x_r[b][d][m] (after pass 2)
__device__ float g_rmax[BB * NN];
__device__ float g_rsinv[BB * NN];

// ======================================================================
// Kernel 1: q = wq @ x ; v = wv @ x + bv      (per batch, per 128-col tile)
// grid (16,16) block 256. smem: xs[128][128], ws[c][r] padded stride 165
// ======================================================================
__global__ __launch_bounds__(256) void k_qv(const float* __restrict__ x,
                                            const float* __restrict__ wq,
                                            const float* __restrict__ wv,
                                            const float* __restrict__ bv) {
    extern __shared__ float sm[];
    float* xs = sm;                 // 128*128
    float* ws = sm + 128 * 128;     // 128 * 165  (ws[c][r], r in [0,160))
    const int b  = blockIdx.y;
    const int n0 = blockIdx.x * NT;
    const int tid = threadIdx.x;
    const float* xb = x + (size_t)b * CC * NN;

    for (int i = tid; i < CC * NT; i += 256) {
        int c = i >> 7, n = i & 127;
        xs[c * NT + n] = xb[(size_t)c * NN + n0 + n];
    }
    for (int i = tid; i < 160 * 128; i += 256) {
        int r = i >> 7, c = i & 127;
        float w = (r < DD) ? wq[r * CC + c] : wv[(r - DD) * CC + c];
        ws[c * 165 + r] = w;
    }
    __syncthreads();

    const int ty = tid >> 4, tx = tid & 15;
    const int r0 = ty * 10, nn = tx * 8;

    float acc[10][8];
#pragma unroll
    for (int i = 0; i < 10; ++i)
#pragma unroll
        for (int j = 0; j < 8; ++j) acc[i][j] = 0.f;

    for (int c = 0; c < CC; ++c) {
        float4 xa = *(const float4*)&xs[c * NT + nn];
        float4 xc = *(const float4*)&xs[c * NT + nn + 4];
        float xv[8] = {xa.x, xa.y, xa.z, xa.w, xc.x, xc.y, xc.z, xc.w};
#pragma unroll
        for (int i = 0; i < 10; ++i) {
            float w = ws[c * 165 + r0 + i];
#pragma unroll
            for (int j = 0; j < 8; ++j) acc[i][j] = fmaf(w, xv[j], acc[i][j]);
        }
    }

    const int gn = n0 + nn;
#pragma unroll
    for (int i = 0; i < 10; ++i) {
        int r = r0 + i;
        if (r < DD) {
            float4 o0 = make_float4(acc[i][0], acc[i][1], acc[i][2], acc[i][3]);
            float4 o1 = make_float4(acc[i][4], acc[i][5], acc[i][6], acc[i][7]);
            float* dst = &g_q[((size_t)b * DD + r) * NN + gn];
            *(float4*)dst = o0;
            *(float4*)(dst + 4) = o1;
        } else {
            int rv = r - DD;
            float bb = bv[rv];
            float4 o0 = make_float4(acc[i][0] + bb, acc[i][1] + bb, acc[i][2] + bb, acc[i][3] + bb);
            float4 o1 = make_float4(acc[i][4] + bb, acc[i][5] + bb, acc[i][6] + bb, acc[i][7] + bb);
            float* dst = &g_v[((size_t)b * CC + rv) * NN + gn];
            *(float4*)dst = o0;
            *(float4*)(dst + 4) = o1;
        }
    }
}

// ======================================================================
// Kernel 2: online row softmax stats of E = q^T q  (rowmax, 1/rowsum)
// grid (16,16) block 256 (16x16 threads, 8x8 microtile)
// ======================================================================
__global__ __launch_bounds__(256) void k_rowstats() {
    extern __shared__ float sm[];
    float* qn = sm;                        // 32*128
    float* qm = sm + DD * NT;              // 32*128
    float2* red = (float2*)(sm + 2 * DD * NT); // 128*16 float2

    const int b  = blockIdx.y;
    const int n0 = blockIdx.x * NT;
    const int tid = threadIdx.x;
    const int ty = tid >> 4, tx = tid & 15;

    for (int i = tid; i < DD * NT; i += 256) {
        int d = i >> 7, j = i & 127;
        qn[i] = g_q[((size_t)b * DD + d) * NN + n0 + j];
    }

    float rmax[8], rsum[8];
#pragma unroll
    for (int i = 0; i < 8; ++i) { rmax[i] = -3.0e38f; rsum[i] = 0.f; }

    for (int mt = 0; mt < NN / NT; ++mt) {
        __syncthreads();
        for (int i = tid; i < DD * NT; i += 256) {
            int d = i >> 7, j = i & 127;
            qm[i] = g_q[((size_t)b * DD + d) * NN + mt * NT + j];
        }
        __syncthreads();

        float e[8][8];
#pragma unroll
        for (int i = 0; i < 8; ++i)
#pragma unroll
            for (int j = 0; j < 8; ++j) e[i][j] = 0.f;

        for (int d = 0; d < DD; ++d) {
            float4 a0 = *(const float4*)&qn[d * NT + ty * 8];
            float4 a1 = *(const float4*)&qn[d * NT + ty * 8 + 4];
            float4 b0 = *(const float4*)&qm[d * NT + tx * 8];
            float4 b1 = *(const float4*)&qm[d * NT + tx * 8 + 4];
            float av[8] = {a0.x, a0.y, a0.z, a0.w, a1.x, a1.y, a1.z, a1.w};
            float bw[8] = {b0.x, b0.y, b0.z, b0.w, b1.x, b1.y, b1.z, b1.w};
#pragma unroll
            for (int i = 0; i < 8; ++i)
#pragma unroll
                for (int j = 0; j < 8; ++j) e[i][j] = fmaf(av[i], bw[j], e[i][j]);
        }

#pragma unroll
        for (int i = 0; i < 8; ++i) {
            float mx = e[i][0];
#pragma unroll
            for (int j = 1; j < 8; ++j) mx = fmaxf(mx, e[i][j]);
            float nm = fmaxf(rmax[i], mx);
            float s = 0.f;
#pragma unroll
            for (int j = 0; j < 8; ++j) s += __expf(e[i][j] - nm);
            rsum[i] = rsum[i] * __expf(rmax[i] - nm) + s;
            rmax[i] = nm;
        }
    }

    __syncthreads();
#pragma unroll
    for (int i = 0; i < 8; ++i)
        red[(ty * 8 + i) * 16 + tx] = make_float2(rmax[i], rsum[i]);
    __syncthreads();

    if (tid < NT) {
        float m = -3.0e38f, l = 0.f;
#pragma unroll
        for (int k = 0; k < 16; ++k) {
            float2 e2 = red[tid * 16 + k];
            float nm = fmaxf(m, e2.x);
            l = l * __expf(m - nm) + e2.y * __expf(e2.x - nm);
            m = nm;
        }
        g_rmax[(size_t)b * NN + n0 + tid] = m;
        g_rsinv[(size_t)b * NN + n0 + tid] = 1.0f / l;
    }
}

// ======================================================================
// Kernel 3: pass 2. For each m-tile: y[d,m] = sum_n v[d,n]*p[n,m],
// c[m] = sum_n p[n,m], p = exp(E - rowmax)*rsinv; write x_r = y/(eps+c)
// grid (16,16) block 256
// ======================================================================
__global__ __launch_bounds__(256) void k_attn() {
    extern __shared__ float sm[];
    float* qm      = sm;            // 4096
    float* qn      = sm + 4096;     // 4096
    float* p       = sm + 8192;     // 16384 (128x128)
    float* vs      = sm + 24576;    // 16512 (128x129), vs[n][d]
    float* rmax_s  = sm + 41088;    // 2048
    float* rsinv_s = sm + 43136;    // 2048
    float* cinv_s  = sm + 45184;    // 128

    const int b  = blockIdx.y;
    const int m0 = blockIdx.x * NT;
    const int tid = threadIdx.x;
    const int ty = tid >> 4, tx = tid & 15;

    for (int i = tid; i < DD * NT; i += 256) {
        int d = i >> 7, j = i & 127;
        qm[i] = g_q[((size_t)b * DD + d) * NN + m0 + j];
    }
    for (int i = tid; i < NN; i += 256) {
        rmax_s[i]  = g_rmax[(size_t)b * NN + i];
        rsinv_s[i] = g_rsinv[(size_t)b * NN + i];
    }

    float y[8][8];
    float csum[8];
#pragma unroll
    for (int i = 0; i < 8; ++i) {
        csum[i] = 0.f;
#pragma unroll
        for (int j = 0; j < 8; ++j) y[i][j] = 0.f;
    }

    for (int nt = 0; nt < NN / NT; ++nt) {
        const int nb = nt * NT;
        __syncthreads();
        for (int i = tid; i < DD * NT; i += 256) {
            int d = i >> 7, j = i & 127;
            qn[i] = g_q[((size_t)b * DD + d) * NN + nb + j];
        }
        for (int i = tid; i < CC * NT; i += 256) {
            int d = i >> 7, j = i & 127;
            vs[j * 129 + d] = g_v[((size_t)b * CC + d) * NN + nb + j];
        }
        __syncthreads();

        // ---- phase A: p tile ----
        float e[8][8];
#pragma unroll
        for (int i = 0; i < 8; ++i)
#pragma unroll
            for (int j = 0; j < 8; ++j) e[i][j] = 0.f;

        for (int d = 0; d < DD; ++d) {
            float4 a0 = *(const float4*)&qn[d * NT + ty * 8];
            float4 a1 = *(const float4*)&qn[d * NT + ty * 8 + 4];
            float4 b0 = *(const float4*)&qm[d * NT + tx * 8];
            float4 b1 = *(const float4*)&qm[d * NT + tx * 8 + 4];
            float av[8] = {a0.x, a0.y, a0.z, a0.w, a1.x, a1.y, a1.z, a1.w};
            float bw[8] = {b0.x, b0.y, b0.z, b0.w, b1.x, b1.y, b1.z, b1.w};
#pragma unroll
            for (int i = 0; i < 8; ++i)
#pragma unroll
                for (int j = 0; j < 8; ++j) e[i][j] = fmaf(av[i], bw[j], e[i][j]);
        }

#pragma unroll
        for (int i = 0; i < 8; ++i) {
            int ni = ty * 8 + i;
            float rm = rmax_s[nb + ni];
            float ri = rsinv_s[nb + ni];
#pragma unroll
            for (int j = 0; j < 8; ++j) {
                float pv = __expf(e[i][j] - rm) * ri;
                e[i][j] = pv;
                csum[j] += pv;
            }
            *(float4*)&p[ni * NT + tx * 8]     = make_float4(e[i][0], e[i][1], e[i][2], e[i][3]);
            *(float4*)&p[ni * NT + tx * 8 + 4] = make_float4(e[i][4], e[i][5], e[i][6], e[i][7]);
        }
        __syncthreads();

        // ---- phase B: y += v @ p ----
        for (int n = 0; n < NT; ++n) {
            float vv[8];
#pragma unroll
            for (int i = 0; i < 8; ++i) vv[i] = vs[n * 129 + ty * 8 + i];
            float4 p0 = *(const float4*)&p[n * NT + tx * 8];
            float4 p1 = *(const float4*)&p[n * NT + tx * 8 + 4];
            float pj[8] = {p0.x, p0.y, p0.z, p0.w, p1.x, p1.y, p1.z, p1.w};
#pragma unroll
            for (int i = 0; i < 8; ++i)
#pragma unroll
                for (int j = 0; j < 8; ++j) y[i][j] = fmaf(vv[i], pj[j], y[i][j]);
        }
    }

    // ---- column-sum reduce over ty, then write x_r = y * cinv ----
    __syncthreads();
#pragma unroll
    for (int j = 0; j < 8; ++j) p[ty * NT + tx * 8 + j] = csum[j];
    __syncthreads();
    if (tid < NT) {
        float c = 0.f;
#pragma unroll
        for (int k = 0; k < 16; ++k) c += p[k * NT + tid];
        cinv_s[tid] = 1.0f / (1e-9f + c);
    }
    __syncthreads();

#pragma unroll
    for (int i = 0; i < 8; ++i) {
        int d = ty * 8 + i;
        float4 o0 = make_float4(y[i][0] * cinv_s[tx * 8 + 0], y[i][1] * cinv_s[tx * 8 + 1],
                                y[i][2] * cinv_s[tx * 8 + 2], y[i][3] * cinv_s[tx * 8 + 3]);
        float4 o1 = make_float4(y[i][4] * cinv_s[tx * 8 + 4], y[i][5] * cinv_s[tx * 8 + 5],
                                y[i][6] * cinv_s[tx * 8 + 6], y[i][7] * cinv_s[tx * 8 + 7]);
        float* dst = &g_y[((size_t)b * CC + d) * NN + m0 + tx * 8];
        *(float4*)dst = o0;
        *(float4*)(dst + 4) = o1;
    }
}

// ======================================================================
// Kernel 4: t = wt @ (x - x_r) + bt ; BN(eval) ; out = x + relu(t)
// grid (16,16) block 256
// ======================================================================
__global__ __launch_bounds__(256) void k_final(const float* __restrict__ x,
                                               const float* __restrict__ wt,
                                               const float* __restrict__ bt,
                                               const float* __restrict__ gamma,
                                               const float* __restrict__ beta,
                                               const float* __restrict__ mean,
                                               const float* __restrict__ var,
                                               float* __restrict__ out) {
    extern __shared__ float sm[];
    float* xms     = sm;             // 16384 (xm[d][m])
    float* wts     = sm + 16384;     // 16512 (wts[d_in][c_out], stride 129)
    float* scale_s = sm + 32896;     // 128
    float* shift_s = sm + 33024;     // 128

    const int b  = blockIdx.y;
    const int m0 = blockIdx.x * NT;
    const int tid = threadIdx.x;
    const int ty = tid >> 4, tx = tid & 15;
    const float* xb = x + (size_t)b * CC * NN;

    for (int i = tid; i < CC * NT; i += 256) {
        int d = i >> 7, j = i & 127;
        xms[i] = xb[(size_t)d * NN + m0 + j] - g_y[((size_t)b * CC + d) * NN + m0 + j];
    }
    for (int i = tid; i < CC * CC; i += 256) {
        int c = i >> 7, d = i & 127;
        wts[d * 129 + c] = wt[i];
    }
    if (tid < CC) {
        float A = gamma[tid] * rsqrtf(var[tid] + 1e-5f);
        scale_s[tid] = A;
        shift_s[tid] = beta[tid] + (bt[tid] - mean[tid]) * A;
    }
    __syncthreads();

    float acc[8][8];
#pragma unroll
    for (int i = 0; i < 8; ++i)
#pragma unroll
        for (int j = 0; j < 8; ++j) acc[i][j] = 0.f;

    for (int d = 0; d < CC; ++d) {
        float wv8[8];
#pragma unroll
        for (int i = 0; i < 8; ++i) wv8[i] = wts[d * 129 + ty * 8 + i];
        float4 x0 = *(const float4*)&xms[d * NT + tx * 8];
        float4 x1 = *(const float4*)&xms[d * NT + tx * 8 + 4];
        float xm8[8] = {x0.x, x0.y, x0.z, x0.w, x1.x, x1.y, x1.z, x1.w};
#pragma unroll
        for (int i = 0; i < 8; ++i)
#pragma unroll
            for (int j = 0; j < 8; ++j) acc[i][j] = fmaf(wv8[i], xm8[j], acc[i][j]);
    }

#pragma unroll
    for (int i = 0; i < 8; ++i) {
        int c = ty * 8 + i;
        float A = scale_s[c], S = shift_s[c];
        const float* xrow = &xb[(size_t)c * NN + m0 + tx * 8];
        float4 xv0 = *(const float4*)xrow;
        float4 xv1 = *(const float4*)(xrow + 4);
        float xv[8] = {xv0.x, xv0.y, xv0.z, xv0.w, xv1.x, xv1.y, xv1.z, xv1.w};
        float o[8];
#pragma unroll
        for (int j = 0; j < 8; ++j) {
            float t = fmaf(acc[i][j], A, S);
            o[j] = xv[j] + fmaxf(t, 0.f);
        }
        float* dst = &out[((size_t)b * CC + c) * NN + m0 + tx * 8];
        *(float4*)dst = make_float4(o[0], o[1], o[2], o[3]);
        *(float4*)(dst + 4) = make_float4(o[4], o[5], o[6], o[7]);
    }
}

// ======================================================================
extern "C" void kernel_launch(void* const* d_in, const int* in_sizes, int n_in,
                              void* d_out, int out_size) {
    const float* x     = (const float*)d_in[0];
    const float* wq    = (const float*)d_in[1];
    const float* wv    = (const float*)d_in[2];
    const float* bv    = (const float*)d_in[3];
    const float* wt    = (const float*)d_in[4];
    const float* bt    = (const float*)d_in[5];
    const float* gamma = (const float*)d_in[6];
    const float* beta  = (const float*)d_in[7];
    const float* mean  = (const float*)d_in[8];
    const float* var   = (const float*)d_in[9];
    float* out = (float*)d_out;

    const int S1 = (128 * 128 + 128 * 165) * 4;                    // 150016
    const int S2 = (2 * DD * NT) * 4 + NT * 16 * 8;                // 49152
    const int S3 = 45312 * 4;                                      // 181248
    const int S4 = 33152 * 4;                                      // 132608

    cudaFuncSetAttribute(k_qv,       cudaFuncAttributeMaxDynamicSharedMemorySize, S1);
    cudaFuncSetAttribute(k_rowstats, cudaFuncAttributeMaxDynamicSharedMemorySize, S2);
    cudaFuncSetAttribute(k_attn,     cudaFuncAttributeMaxDynamicSharedMemorySize, S3);
    cudaFuncSetAttribute(k_final,    cudaFuncAttributeMaxDynamicSharedMemorySize, S4);

    dim3 grid(NN / NT, BB);
    k_qv<<<grid, 256, S1>>>(x, wq, wv, bv);
    k_rowstats<<<grid, 256, S2>>>();
    k_attn<<<grid, 256, S3>>>();
    k_final<<<grid, 256, S4>>>(x, wt, bt, gamma, beta, mean, var, out);
}

// round 3
// speedup vs baseline: 2.4673x; 2.4673x over previous
#include <cuda_runtime.h>
#include <cstdint>

#define BB 16
#define CC 128
#define DD 32
#define NN 2048
#define NT 128
#define SQRT_LOG2E 1.2011224087864498f

// ---------------- device scratch (static) ----------------
__device__ float g_qs[BB * NN * DD];   // qT[b][n][d], *sqrt(log2e), tf32-rounded
__device__ float g_v [BB * CC * NN];   // v[b][c][n], tf32-rounded
__device__ float g_rsinv[BB * NN];     // 1/rowsum

// ---------------- helpers ----------------
__device__ __forceinline__ float to_tf32(float x) {
    uint32_t u; asm("cvt.rna.tf32.f32 %0, %1;" : "=r"(u) : "f"(x));
    return __uint_as_float(u);
}
__device__ __forceinline__ float ex2f(float x) {
    float y; asm("ex2.approx.ftz.f32 %0, %1;" : "=f"(y) : "f"(x)); return y;
}
__device__ __forceinline__ void mma8(float c[4],
                                     uint32_t a0, uint32_t a1, uint32_t a2, uint32_t a3,
                                     uint32_t b0, uint32_t b1) {
    asm volatile(
        "mma.sync.aligned.m16n8k8.row.col.f32.tf32.tf32.f32 "
        "{%0,%1,%2,%3}, {%4,%5,%6,%7}, {%8,%9}, {%0,%1,%2,%3};"
        : "+f"(c[0]), "+f"(c[1]), "+f"(c[2]), "+f"(c[3])
        : "r"(a0), "r"(a1), "r"(a2), "r"(a3), "r"(b0), "r"(b1));
}
__device__ __forceinline__ uint32_t fu(float f) { return __float_as_uint(f); }

// ======================================================================
// k1: q = wq@x (scaled, transposed, tf32) ; v = wv@x + bv (tf32)
// 512 threads, grid (16,16)
// ======================================================================
__global__ __launch_bounds__(512) void k_qv(const float* __restrict__ x,
                                            const float* __restrict__ wq,
                                            const float* __restrict__ wv,
                                            const float* __restrict__ bv) {
    extern __shared__ float sm[];
    float* xs = sm;                  // 128*128
    float* ws = sm + 16384;          // 128*165  ws[c][r], r in [0,160)
    float* qb = sm + 16384 + 21120;  // 32*129
    const int b  = blockIdx.y;
    const int n0 = blockIdx.x * NT;
    const int tid = threadIdx.x;
    const float* xb = x + (size_t)b * CC * NN;

    for (int i = tid; i < CC * NT; i += 512) {
        int c = i >> 7, n = i & 127;
        xs[c * NT + n] = xb[(size_t)c * NN + n0 + n];
    }
    for (int i = tid; i < 160 * 128; i += 512) {
        int r = i >> 7, c = i & 127;
        float w = (r < DD) ? wq[r * CC + c] : wv[(r - DD) * CC + c];
        ws[c * 165 + r] = w;
    }
    __syncthreads();

    const int ty = tid >> 5, tx = tid & 31;   // 16 x 32
    const int r0 = ty * 10, nn = tx * 4;

    float acc[10][4];
#pragma unroll
    for (int i = 0; i < 10; ++i)
#pragma unroll
        for (int j = 0; j < 4; ++j) acc[i][j] = 0.f;

    for (int c = 0; c < CC; ++c) {
        float4 xa = *(const float4*)&xs[c * NT + nn];
        float xv[4] = {xa.x, xa.y, xa.z, xa.w};
#pragma unroll
        for (int i = 0; i < 10; ++i) {
            float w = ws[c * 165 + r0 + i];
#pragma unroll
            for (int j = 0; j < 4; ++j) acc[i][j] = fmaf(w, xv[j], acc[i][j]);
        }
    }

    const int gn = n0 + nn;
#pragma unroll
    for (int i = 0; i < 10; ++i) {
        int r = r0 + i;
        if (r < DD) {
#pragma unroll
            for (int j = 0; j < 4; ++j) qb[r * 129 + nn + j] = acc[i][j];
        } else {
            int rv = r - DD;
            float bb = bv[rv];
            float4 o = make_float4(to_tf32(acc[i][0] + bb), to_tf32(acc[i][1] + bb),
                                   to_tf32(acc[i][2] + bb), to_tf32(acc[i][3] + bb));
            *(float4*)&g_v[((size_t)b * CC + rv) * NN + gn] = o;
        }
    }
    __syncthreads();
    for (int i = tid; i < DD * NT; i += 512) {
        int n = i >> 5, d = i & 31;
        g_qs[((size_t)b * NN + n0 + n) * DD + d] = to_tf32(qb[d * 129 + n] * SQRT_LOG2E);
    }
}

// ======================================================================
// k2: rowsum[n] = sum_m exp2(E[n,m]); store 1/rowsum.  256 threads.
// E via mma.sync tf32, warp tile 32x64.
// ======================================================================
__global__ __launch_bounds__(256) void k_rowsum() {
    extern __shared__ float sm[];
    float* red  = sm;             // 128
    float* qn_s = sm + 128;       // 128*36
    float* qm_s = qn_s + 128 * 36;

    const int tid = threadIdx.x, w = tid >> 5, lane = tid & 31;
    const int row0 = (w & 3) * 32, col0 = (w >> 2) * 64;
    const int qr = lane >> 2, ql = lane & 3;
    const int b = blockIdx.y, n0 = blockIdx.x * NT;

    if (tid < 128) red[tid] = 0.f;
    for (int i = tid; i < NT * DD; i += 256) {
        int r = i >> 5, d = i & 31;
        qn_s[r * 36 + d] = g_qs[((size_t)b * NN + n0 + r) * DD + d];
    }

    float racc[2][2] = {};

    for (int mt = 0; mt < NN / NT; ++mt) {
        __syncthreads();
        for (int i = tid; i < NT * DD; i += 256) {
            int r = i >> 5, d = i & 31;
            qm_s[r * 36 + d] = g_qs[((size_t)b * NN + mt * NT + r) * DD + d];
        }
        __syncthreads();

        float e[2][8][4] = {};
#pragma unroll
        for (int ks = 0; ks < 4; ++ks) {
            const int k0 = ks * 8;
            uint32_t A[2][4];
#pragma unroll
            for (int mi = 0; mi < 2; ++mi) {
                int r = row0 + mi * 16 + qr;
                A[mi][0] = fu(qn_s[r * 36 + k0 + ql]);
                A[mi][1] = fu(qn_s[(r + 8) * 36 + k0 + ql]);
                A[mi][2] = fu(qn_s[r * 36 + k0 + 4 + ql]);
                A[mi][3] = fu(qn_s[(r + 8) * 36 + k0 + 4 + ql]);
            }
#pragma unroll
            for (int ni = 0; ni < 8; ++ni) {
                int cb = col0 + ni * 8 + qr;
                uint32_t b0 = fu(qm_s[cb * 36 + k0 + ql]);
                uint32_t b1 = fu(qm_s[cb * 36 + k0 + 4 + ql]);
                mma8(e[0][ni], A[0][0], A[0][1], A[0][2], A[0][3], b0, b1);
                mma8(e[1][ni], A[1][0], A[1][1], A[1][2], A[1][3], b0, b1);
            }
        }
#pragma unroll
        for (int mi = 0; mi < 2; ++mi)
#pragma unroll
            for (int ni = 0; ni < 8; ++ni) {
                racc[mi][0] += ex2f(e[mi][ni][0]) + ex2f(e[mi][ni][1]);
                racc[mi][1] += ex2f(e[mi][ni][2]) + ex2f(e[mi][ni][3]);
            }
    }

#pragma unroll
    for (int mi = 0; mi < 2; ++mi)
#pragma unroll
        for (int h = 0; h < 2; ++h) {
            float v = racc[mi][h];
            v += __shfl_xor_sync(0xffffffffu, v, 1);
            v += __shfl_xor_sync(0xffffffffu, v, 2);
            racc[mi][h] = v;
        }
    if (ql == 0) {
        atomicAdd(&red[row0 + qr],          racc[0][0]);
        atomicAdd(&red[row0 + qr + 8],      racc[0][1]);
        atomicAdd(&red[row0 + 16 + qr],     racc[1][0]);
        atomicAdd(&red[row0 + 16 + qr + 8], racc[1][1]);
    }
    __syncthreads();
    if (tid < 128) g_rsinv[(size_t)b * NN + n0 + tid] = 1.0f / red[tid];
}

// ======================================================================
// k3: fused attention + epilogue. 256 threads, grid (16,16).
// per (b, m-tile): loop n { E mma -> p = ex2(e)*rsinv (csum in regs)
//   -> pT smem -> Y += v@p mma }  then cinv, xm = x - Y*cinv, t = wt@xm,
//   out = x + relu(BN(t)).
// ======================================================================
__global__ __launch_bounds__(256, 1) void k_attn(const float* __restrict__ x,
                                                 const float* __restrict__ wt,
                                                 const float* __restrict__ bt,
                                                 const float* __restrict__ gamma,
                                                 const float* __restrict__ beta,
                                                 const float* __restrict__ mean,
                                                 const float* __restrict__ var,
                                                 float* __restrict__ out) {
    extern __shared__ float sm[];
    float* csum_s  = sm;            // 128
    float* cinv_s  = sm + 128;      // 128
    float* A_s     = sm + 256;      // 128
    float* S_s     = sm + 384;      // 128
    float* rsinv_s = sm + 512;      // 128
    float* qm_s    = sm + 640;      // 128*36 = 4608
    float* qn_s    = qm_s + 4608;   // 4608
    float* vs      = qn_s + 4608;   // 128*132 = 16896 (also wt_s in epilogue)
    float* pT      = vs + 16896;    // 16896 (also xm_s in epilogue)

    const int tid = threadIdx.x, w = tid >> 5, lane = tid & 31;
    const int row0 = (w & 3) * 32, col0 = (w >> 2) * 64;
    const int qr = lane >> 2, ql = lane & 3;
    const int b = blockIdx.y, m0 = blockIdx.x * NT;

    if (tid < 128) {
        csum_s[tid] = 0.f;
        float A = gamma[tid] * rsqrtf(var[tid] + 1e-5f);
        A_s[tid] = A;
        S_s[tid] = beta[tid] + (bt[tid] - mean[tid]) * A;
    }
    for (int i = tid; i < NT * DD; i += 256) {
        int r = i >> 5, d = i & 31;
        qm_s[r * 36 + d] = g_qs[((size_t)b * NN + m0 + r) * DD + d];
    }

    float yacc[2][8][4] = {};
    float csum[16] = {};

    for (int nt = 0; nt < NN / NT; ++nt) {
        const int nb = nt * NT;
        __syncthreads();
        for (int i = tid; i < NT * DD; i += 256) {
            int r = i >> 5, d = i & 31;
            qn_s[r * 36 + d] = g_qs[((size_t)b * NN + nb + r) * DD + d];
        }
        for (int i = tid; i < CC * NT; i += 256) {
            int c = i >> 7, nl = i & 127;
            vs[c * 132 + nl] = g_v[((size_t)b * CC + c) * NN + nb + nl];
        }
        if (tid < 128) rsinv_s[tid] = g_rsinv[(size_t)b * NN + nb + tid];
        __syncthreads();

        // ---- E = qn . qm^T  (rows n, cols m), K = 32 ----
        float e[2][8][4] = {};
#pragma unroll
        for (int ks = 0; ks < 4; ++ks) {
            const int k0 = ks * 8;
            uint32_t A[2][4];
#pragma unroll
            for (int mi = 0; mi < 2; ++mi) {
                int r = row0 + mi * 16 + qr;
                A[mi][0] = fu(qn_s[r * 36 + k0 + ql]);
                A[mi][1] = fu(qn_s[(r + 8) * 36 + k0 + ql]);
                A[mi][2] = fu(qn_s[r * 36 + k0 + 4 + ql]);
                A[mi][3] = fu(qn_s[(r + 8) * 36 + k0 + 4 + ql]);
            }
#pragma unroll
            for (int ni = 0; ni < 8; ++ni) {
                int cb = col0 + ni * 8 + qr;
                uint32_t b0 = fu(qm_s[cb * 36 + k0 + ql]);
                uint32_t b1 = fu(qm_s[cb * 36 + k0 + 4 + ql]);
                mma8(e[0][ni], A[0][0], A[0][1], A[0][2], A[0][3], b0, b1);
                mma8(e[1][ni], A[1][0], A[1][1], A[1][2], A[1][3], b0, b1);
            }
        }

        // ---- p = ex2(e) * rsinv[n]; csum += p; store pT[m][n] ----
#pragma unroll
        for (int mi = 0; mi < 2; ++mi) {
            int r = row0 + mi * 16 + qr;
            float ri0 = rsinv_s[r], ri1 = rsinv_s[r + 8];
#pragma unroll
            for (int ni = 0; ni < 8; ++ni) {
                int col = col0 + ni * 8 + 2 * ql;
                float p00 = ex2f(e[mi][ni][0]) * ri0;
                float p01 = ex2f(e[mi][ni][1]) * ri0;
                float p10 = ex2f(e[mi][ni][2]) * ri1;
                float p11 = ex2f(e[mi][ni][3]) * ri1;
                csum[ni * 2]     += p00 + p10;
                csum[ni * 2 + 1] += p01 + p11;
                pT[col * 132 + r]           = to_tf32(p00);
                pT[(col + 1) * 132 + r]     = to_tf32(p01);
                pT[col * 132 + r + 8]       = to_tf32(p10);
                pT[(col + 1) * 132 + r + 8] = to_tf32(p11);
            }
        }
        __syncthreads();

        // ---- Y += v @ p  (rows c, cols m), K = 128 ----
#pragma unroll
        for (int ks = 0; ks < 16; ++ks) {
            const int k0 = ks * 8;
            uint32_t A[2][4];
#pragma unroll
            for (int mi = 0; mi < 2; ++mi) {
                int r = row0 + mi * 16 + qr;
                A[mi][0] = fu(vs[r * 132 + k0 + ql]);
                A[mi][1] = fu(vs[(r + 8) * 132 + k0 + ql]);
                A[mi][2] = fu(vs[r * 132 + k0 + 4 + ql]);
                A[mi][3] = fu(vs[(r + 8) * 132 + k0 + 4 + ql]);
            }
#pragma unroll
            for (int ni = 0; ni < 8; ++ni) {
                int cb = col0 + ni * 8 + qr;
                uint32_t b0 = fu(pT[cb * 132 + k0 + ql]);
                uint32_t b1 = fu(pT[cb * 132 + k0 + 4 + ql]);
                mma8(yacc[0][ni], A[0][0], A[0][1], A[0][2], A[0][3], b0, b1);
                mma8(yacc[1][ni], A[1][0], A[1][1], A[1][2], A[1][3], b0, b1);
            }
        }
    }

    // ---------------- epilogue ----------------
    __syncthreads();
#pragma unroll
    for (int i = 0; i < 16; ++i) {
        float v = csum[i];
        v += __shfl_xor_sync(0xffffffffu, v, 4);
        v += __shfl_xor_sync(0xffffffffu, v, 8);
        v += __shfl_xor_sync(0xffffffffu, v, 16);
        if (qr == 0) atomicAdd(&csum_s[col0 + (i >> 1) * 8 + 2 * ql + (i & 1)], v);
    }
    __syncthreads();
    if (tid < 128) cinv_s[tid] = 1.0f / (1e-9f + csum_s[tid]);
    for (int i = tid; i < CC * CC; i += 256) {
        int co = i >> 7, ci = i & 127;
        vs[co * 132 + ci] = to_tf32(wt[i]);
    }
    __syncthreads();

    // xm[c][m] = x - Y*cinv  -> pT[m][c]
    const float* xb = x + ((size_t)b * CC) * NN + m0;
#pragma unroll
    for (int mi = 0; mi < 2; ++mi) {
        int r = row0 + mi * 16 + qr;
#pragma unroll
        for (int ni = 0; ni < 8; ++ni) {
            int col = col0 + ni * 8 + 2 * ql;
            float2 x0 = __ldg((const float2*)&xb[(size_t)r * NN + col]);
            float2 x1 = __ldg((const float2*)&xb[(size_t)(r + 8) * NN + col]);
            float ci0 = cinv_s[col], ci1 = cinv_s[col + 1];
            pT[col * 132 + r]           = to_tf32(x0.x - yacc[mi][ni][0] * ci0);
            pT[(col + 1) * 132 + r]     = to_tf32(x0.y - yacc[mi][ni][1] * ci1);
            pT[col * 132 + r + 8]       = to_tf32(x1.x - yacc[mi][ni][2] * ci0);
            pT[(col + 1) * 132 + r + 8] = to_tf32(x1.y - yacc[mi][ni][3] * ci1);
        }
    }
    __syncthreads();

    // t = wt @ xm   (rows c_out, cols m), K = 128
    float tacc[2][8][4] = {};
#pragma unroll
    for (int ks = 0; ks < 16; ++ks) {
        const int k0 = ks * 8;
        uint32_t A[2][4];
#pragma unroll
        for (int mi = 0; mi < 2; ++mi) {
            int r = row0 + mi * 16 + qr;
            A[mi][0] = fu(vs[r * 132 + k0 + ql]);
            A[mi][1] = fu(vs[(r + 8) * 132 + k0 + ql]);
            A[mi][2] = fu(vs[r * 132 + k0 + 4 + ql]);
            A[mi][3] = fu(vs[(r + 8) * 132 + k0 + 4 + ql]);
        }
#pragma unroll
        for (int ni = 0; ni < 8; ++ni) {
            int cb = col0 + ni * 8 + qr;
            uint32_t b0 = fu(pT[cb * 132 + k0 + ql]);
            uint32_t b1 = fu(pT[cb * 132 + k0 + 4 + ql]);
            mma8(tacc[0][ni], A[0][0], A[0][1], A[0][2], A[0][3], b0, b1);
            mma8(tacc[1][ni], A[1][0], A[1][1], A[1][2], A[1][3], b0, b1);
        }
    }

    // out = x + relu(t*A + S)
#pragma unroll
    for (int mi = 0; mi < 2; ++mi) {
        int r = row0 + mi * 16 + qr;
        float a0 = A_s[r], s0 = S_s[r];
        float a1 = A_s[r + 8], s1 = S_s[r + 8];
#pragma unroll
        for (int ni = 0; ni < 8; ++ni) {
            int col = col0 + ni * 8 + 2 * ql;
            float2 x0 = __ldg((const float2*)&xb[(size_t)r * NN + col]);
            float2 x1 = __ldg((const float2*)&xb[(size_t)(r + 8) * NN + col]);
            float2 o0, o1;
            o0.x = x0.x + fmaxf(fmaf(tacc[mi][ni][0], a0, s0), 0.f);
            o0.y = x0.y + fmaxf(fmaf(tacc[mi][ni][1], a0, s0), 0.f);
            o1.x = x1.x + fmaxf(fmaf(tacc[mi][ni][2], a1, s1), 0.f);
            o1.y = x1.y + fmaxf(fmaf(tacc[mi][ni][3], a1, s1), 0.f);
            *(float2*)&out[((size_t)b * CC + r) * NN + m0 + col]     = o0;
            *(float2*)&out[((size_t)b * CC + r + 8) * NN + m0 + col] = o1;
        }
    }
}

// ======================================================================
extern "C" void kernel_launch(void* const* d_in, const int* in_sizes, int n_in,
                              void* d_out, int out_size) {
    const float* x     = (const float*)d_in[0];
    const float* wq    = (const float*)d_in[1];
    const float* wv    = (const float*)d_in[2];
    const float* bv    = (const float*)d_in[3];
    const float* wt    = (const float*)d_in[4];
    const float* bt    = (const float*)d_in[5];
    const float* gamma = (const float*)d_in[6];
    const float* beta  = (const float*)d_in[7];
    const float* mean  = (const float*)d_in[8];
    const float* var   = (const float*)d_in[9];
    float* out = (float*)d_out;

    const int S1 = (16384 + 21120 + 4128) * 4;            // 166528
    const int S2 = (128 + 2 * 128 * 36) * 4;              // 37376
    const int S3 = (640 + 2 * 4608 + 2 * 16896) * 4;      // 174592

    cudaFuncSetAttribute(k_qv,     cudaFuncAttributeMaxDynamicSharedMemorySize, S1);
    cudaFuncSetAttribute(k_rowsum, cudaFuncAttributeMaxDynamicSharedMemorySize, S2);
    cudaFuncSetAttribute(k_attn,   cudaFuncAttributeMaxDynamicSharedMemorySize, S3);

    dim3 grid(NN / NT, BB);
    k_qv<<<grid, 512, S1>>>(x, wq, wv, bv);
    k_rowsum<<<grid, 256, S2>>>();
    k_attn<<<grid, 256, S3>>>(x, wt, bt, gamma, beta, mean, var, out);
}

// round 4
// speedup vs baseline: 3.8944x; 1.5784x over previous
#include <cuda_runtime.h>
#include <cstdint>

#define BB 16
#define CC 128
#define DD 32
#define NN 2048
#define NT 128
#define SQRT_LOG2E 1.2011224087864498f

// ---------------- device scratch (static) ----------------
__device__ float g_qs[BB * NN * DD];   // qT[b][n][d], *sqrt(log2e), tf32-rounded
__device__ float g_v [BB * CC * NN];   // v[b][c][n], tf32-rounded
__device__ float g_rsinv[BB * NN];     // 1/rowsum

// ---------------- helpers ----------------
__device__ __forceinline__ float to_tf32(float x) {
    uint32_t u; asm("cvt.rna.tf32.f32 %0, %1;" : "=r"(u) : "f"(x));
    return __uint_as_float(u);
}
__device__ __forceinline__ float ex2f(float x) {
    float y; asm("ex2.approx.ftz.f32 %0, %1;" : "=f"(y) : "f"(x)); return y;
}
__device__ __forceinline__ void mma8(float c[4],
                                     uint32_t a0, uint32_t a1, uint32_t a2, uint32_t a3,
                                     uint32_t b0, uint32_t b1) {
    asm volatile(
        "mma.sync.aligned.m16n8k8.row.col.f32.tf32.tf32.f32 "
        "{%0,%1,%2,%3}, {%4,%5,%6,%7}, {%8,%9}, {%0,%1,%2,%3};"
        : "+f"(c[0]), "+f"(c[1]), "+f"(c[2]), "+f"(c[3])
        : "r"(a0), "r"(a1), "r"(a2), "r"(a3), "r"(b0), "r"(b1));
}
__device__ __forceinline__ uint32_t fu(float f) { return __float_as_uint(f); }
__device__ __forceinline__ uint32_t smem_u32(const void* p) {
    uint32_t a;
    asm("{ .reg .u64 t; cvta.to.shared.u64 t, %1; cvt.u32.u64 %0, t; }" : "=r"(a) : "l"(p));
    return a;
}
__device__ __forceinline__ void cpa16(uint32_t dst, const float* src) {
    asm volatile("cp.async.cg.shared.global [%0], [%1], 16;" :: "r"(dst), "l"(src));
}
#define CPA_COMMIT() asm volatile("cp.async.commit_group;" ::: "memory")
#define CPA_WAIT(n)  asm volatile("cp.async.wait_group %0;" :: "n"(n) : "memory")

// ======================================================================
// k1: q = wq@x (scaled, transposed, tf32) ; v = wv@x + bv (tf32)
// tf32 mma. 320 threads (10 warps: 5 row-groups x 2 col-groups of 32x64).
// ======================================================================
__global__ __launch_bounds__(320) void k_qv(const float* __restrict__ x,
                                            const float* __restrict__ wq,
                                            const float* __restrict__ wv,
                                            const float* __restrict__ bv) {
    extern __shared__ float sm[];
    float* xT   = sm;             // 128*132  xT[n][c]
    float* ws   = sm + 16896;     // 160*132  ws[r][c]
    float* qb   = sm + 38016;     // 32*129
    float* bv_s = sm + 42144;     // 128
    const int b  = blockIdx.y;
    const int n0 = blockIdx.x * NT;
    const int tid = threadIdx.x;
    const float* xb = x + (size_t)b * CC * NN;

    for (int i = tid; i < CC * NT; i += 320) {
        int c = i >> 7, n = i & 127;
        xT[n * 132 + c] = xb[(size_t)c * NN + n0 + n];
    }
    for (int i = tid; i < 160 * 128; i += 320) {
        int r = i >> 7, c = i & 127;
        ws[r * 132 + c] = (r < DD) ? wq[r * CC + c] : wv[(r - DD) * CC + c];
    }
    if (tid < CC) bv_s[tid] = bv[tid];
    __syncthreads();

    const int w = tid >> 5, lane = tid & 31;
    const int rg = w >> 1, cg = w & 1;
    const int row0 = rg * 32, col0 = cg * 64;
    const int qr = lane >> 2, ql = lane & 3;

    float acc[2][8][4] = {};
#pragma unroll
    for (int ks = 0; ks < 16; ++ks) {
        const int k0 = ks * 8;
        uint32_t A[2][4];
#pragma unroll
        for (int mi = 0; mi < 2; ++mi) {
            int r = row0 + mi * 16 + qr;
            A[mi][0] = fu(ws[r * 132 + k0 + ql]);
            A[mi][1] = fu(ws[(r + 8) * 132 + k0 + ql]);
            A[mi][2] = fu(ws[r * 132 + k0 + 4 + ql]);
            A[mi][3] = fu(ws[(r + 8) * 132 + k0 + 4 + ql]);
        }
#pragma unroll
        for (int ni = 0; ni < 8; ++ni) {
            int cb = col0 + ni * 8 + qr;
            uint32_t b0 = fu(xT[cb * 132 + k0 + ql]);
            uint32_t b1 = fu(xT[cb * 132 + k0 + 4 + ql]);
            mma8(acc[0][ni], A[0][0], A[0][1], A[0][2], A[0][3], b0, b1);
            mma8(acc[1][ni], A[1][0], A[1][1], A[1][2], A[1][3], b0, b1);
        }
    }

    if (rg == 0) {
        // q rows: d = 0..31 -> qb[d][n], scaled + tf32
#pragma unroll
        for (int mi = 0; mi < 2; ++mi) {
            int d = mi * 16 + qr;
#pragma unroll
            for (int ni = 0; ni < 8; ++ni) {
                int col = col0 + ni * 8 + 2 * ql;
                qb[d * 129 + col]           = to_tf32(acc[mi][ni][0] * SQRT_LOG2E);
                qb[d * 129 + col + 1]       = to_tf32(acc[mi][ni][1] * SQRT_LOG2E);
                qb[(d + 8) * 129 + col]     = to_tf32(acc[mi][ni][2] * SQRT_LOG2E);
                qb[(d + 8) * 129 + col + 1] = to_tf32(acc[mi][ni][3] * SQRT_LOG2E);
            }
        }
    } else {
        // v rows: rv = row0-32 ..
#pragma unroll
        for (int mi = 0; mi < 2; ++mi) {
            int rv = row0 - DD + mi * 16 + qr;
            float b0v = bv_s[rv], b1v = bv_s[rv + 8];
#pragma unroll
            for (int ni = 0; ni < 8; ++ni) {
                int col = col0 + ni * 8 + 2 * ql;
                float2 o0 = make_float2(to_tf32(acc[mi][ni][0] + b0v), to_tf32(acc[mi][ni][1] + b0v));
                float2 o1 = make_float2(to_tf32(acc[mi][ni][2] + b1v), to_tf32(acc[mi][ni][3] + b1v));
                *(float2*)&g_v[((size_t)b * CC + rv) * NN + n0 + col]     = o0;
                *(float2*)&g_v[((size_t)b * CC + rv + 8) * NN + n0 + col] = o1;
            }
        }
    }
    __syncthreads();
    for (int i = tid; i < NT * DD; i += 320) {
        int n = i >> 5, d = i & 31;
        g_qs[((size_t)b * NN + n0 + n) * DD + d] = qb[d * 129 + n];
    }
}

// ======================================================================
// k2: rowsum[n] = sum_m exp2(E[n,m]); 512 threads, 32x32 warp tiles,
// double-buffered qm via cp.async.
// ======================================================================
__global__ __launch_bounds__(512) void k_rowsum() {
    extern __shared__ float sm[];
    float* red  = sm;              // 128
    float* qn_s = sm + 128;        // 128*36
    float* qm0  = sm + 128 + 4608;
    float* qm1  = qm0 + 4608;

    const int tid = threadIdx.x, w = tid >> 5, lane = tid & 31;
    const int row0 = (w & 3) * 32, col0 = (w >> 2) * 32;
    const int qr = lane >> 2, ql = lane & 3;
    const int b = blockIdx.y, n0 = blockIdx.x * NT;
    const uint32_t qm0u = smem_u32(qm0), qm1u = smem_u32(qm1);

    if (tid < 128) red[tid] = 0.f;
    for (int i = tid; i < NT * DD; i += 512) {
        int r = i >> 5, d = i & 31;
        qn_s[r * 36 + d] = g_qs[((size_t)b * NN + n0 + r) * DD + d];
    }
    // prologue: prefetch qm(0) into qm0
#pragma unroll
    for (int k = 0; k < 2; ++k) {
        int idx4 = tid + k * 512;
        int r = idx4 >> 3, d4 = (idx4 & 7) << 2;
        cpa16(qm0u + (r * 36 + d4) * 4, &g_qs[((size_t)b * NN + r) * DD + d4]);
    }
    CPA_COMMIT();

    float racc[2][2] = {};
    for (int mt = 0; mt < NN / NT; ++mt) {
        const float* qm = (mt & 1) ? qm1 : qm0;
        const uint32_t qmnu = (mt & 1) ? qm0u : qm1u;
        CPA_WAIT(0);
        __syncthreads();
        if (mt + 1 < NN / NT) {
#pragma unroll
            for (int k = 0; k < 2; ++k) {
                int idx4 = tid + k * 512;
                int r = idx4 >> 3, d4 = (idx4 & 7) << 2;
                cpa16(qmnu + (r * 36 + d4) * 4,
                      &g_qs[((size_t)b * NN + (mt + 1) * NT + r) * DD + d4]);
            }
            CPA_COMMIT();
        }

        float e[2][4][4] = {};
#pragma unroll
        for (int ks = 0; ks < 4; ++ks) {
            const int k0 = ks * 8;
            uint32_t A[2][4];
#pragma unroll
            for (int mi = 0; mi < 2; ++mi) {
                int r = row0 + mi * 16 + qr;
                A[mi][0] = fu(qn_s[r * 36 + k0 + ql]);
                A[mi][1] = fu(qn_s[(r + 8) * 36 + k0 + ql]);
                A[mi][2] = fu(qn_s[r * 36 + k0 + 4 + ql]);
                A[mi][3] = fu(qn_s[(r + 8) * 36 + k0 + 4 + ql]);
            }
#pragma unroll
            for (int ni = 0; ni < 4; ++ni) {
                int cb = col0 + ni * 8 + qr;
                uint32_t b0 = fu(qm[cb * 36 + k0 + ql]);
                uint32_t b1 = fu(qm[cb * 36 + k0 + 4 + ql]);
                mma8(e[0][ni], A[0][0], A[0][1], A[0][2], A[0][3], b0, b1);
                mma8(e[1][ni], A[1][0], A[1][1], A[1][2], A[1][3], b0, b1);
            }
        }
#pragma unroll
        for (int mi = 0; mi < 2; ++mi)
#pragma unroll
            for (int ni = 0; ni < 4; ++ni) {
                racc[mi][0] += ex2f(e[mi][ni][0]) + ex2f(e[mi][ni][1]);
                racc[mi][1] += ex2f(e[mi][ni][2]) + ex2f(e[mi][ni][3]);
            }
    }

#pragma unroll
    for (int mi = 0; mi < 2; ++mi)
#pragma unroll
        for (int h = 0; h < 2; ++h) {
            float v = racc[mi][h];
            v += __shfl_xor_sync(0xffffffffu, v, 1);
            v += __shfl_xor_sync(0xffffffffu, v, 2);
            racc[mi][h] = v;
        }
    if (ql == 0) {
        atomicAdd(&red[row0 + qr],          racc[0][0]);
        atomicAdd(&red[row0 + qr + 8],      racc[0][1]);
        atomicAdd(&red[row0 + 16 + qr],     racc[1][0]);
        atomicAdd(&red[row0 + 16 + qr + 8], racc[1][1]);
    }
    __syncthreads();
    if (tid < 128) g_rsinv[(size_t)b * NN + n0 + tid] = 1.0f / red[tid];
}

// ======================================================================
// k3: fused attention + epilogue. 512 threads (16 warps, 32x32 tiles),
// cp.async pipelined staging.
// ======================================================================
__global__ __launch_bounds__(512, 1) void k_attn(const float* __restrict__ x,
                                                 const float* __restrict__ wt,
                                                 const float* __restrict__ bt,
                                                 const float* __restrict__ gamma,
                                                 const float* __restrict__ beta,
                                                 const float* __restrict__ mean,
                                                 const float* __restrict__ var,
                                                 float* __restrict__ out) {
    extern __shared__ float sm[];
    float* csum_s  = sm;            // 128
    float* cinv_s  = sm + 128;      // 128
    float* A_s     = sm + 256;      // 128
    float* S_s     = sm + 384;      // 128
    float* rsinv_s = sm + 512;      // 128
    float* qm_s    = sm + 640;      // 4608
    float* qn_s    = sm + 5248;     // 4608
    float* vs      = sm + 9856;     // 16896 (wt_s in epilogue)
    float* pT      = sm + 26752;    // 16896 (xm_s in epilogue)

    const int tid = threadIdx.x, w = tid >> 5, lane = tid & 31;
    const int row0 = (w & 3) * 32, col0 = (w >> 2) * 32;
    const int qr = lane >> 2, ql = lane & 3;
    const int b = blockIdx.y, m0 = blockIdx.x * NT;
    const uint32_t qn_u = smem_u32(qn_s), vs_u = smem_u32(vs);

    if (tid < 128) {
        csum_s[tid] = 0.f;
        float A = gamma[tid] * rsqrtf(var[tid] + 1e-5f);
        A_s[tid] = A;
        S_s[tid] = beta[tid] + (bt[tid] - mean[tid]) * A;
    }
    for (int i = tid; i < NT * DD; i += 512) {
        int r = i >> 5, d = i & 31;
        qm_s[r * 36 + d] = g_qs[((size_t)b * NN + m0 + r) * DD + d];
    }
    // prologue prefetch: qn(0) group, vs(0) group
#pragma unroll
    for (int k = 0; k < 2; ++k) {
        int idx4 = tid + k * 512;
        int r = idx4 >> 3, d4 = (idx4 & 7) << 2;
        cpa16(qn_u + (r * 36 + d4) * 4, &g_qs[((size_t)b * NN + r) * DD + d4]);
    }
    CPA_COMMIT();
#pragma unroll
    for (int k = 0; k < 8; ++k) {
        int idx4 = tid + k * 512;
        int c = idx4 >> 5, n4 = (idx4 & 31) << 2;
        cpa16(vs_u + (c * 132 + n4) * 4, &g_v[((size_t)b * CC + c) * NN + n4]);
    }
    CPA_COMMIT();

    float yacc[2][4][4] = {};
    float csum[8] = {};

    for (int nt = 0; nt < NN / NT; ++nt) {
        const int nb = nt * NT;
        if (tid < 128) rsinv_s[tid] = g_rsinv[(size_t)b * NN + nb + tid];
        CPA_WAIT(1);                 // qn(nt) ready
        __syncthreads();

        // ---- E = qn . qm^T ----
        float e[2][4][4] = {};
#pragma unroll
        for (int ks = 0; ks < 4; ++ks) {
            const int k0 = ks * 8;
            uint32_t A[2][4];
#pragma unroll
            for (int mi = 0; mi < 2; ++mi) {
                int r = row0 + mi * 16 + qr;
                A[mi][0] = fu(qn_s[r * 36 + k0 + ql]);
                A[mi][1] = fu(qn_s[(r + 8) * 36 + k0 + ql]);
                A[mi][2] = fu(qn_s[r * 36 + k0 + 4 + ql]);
                A[mi][3] = fu(qn_s[(r + 8) * 36 + k0 + 4 + ql]);
            }
#pragma unroll
            for (int ni = 0; ni < 4; ++ni) {
                int cb = col0 + ni * 8 + qr;
                uint32_t b0 = fu(qm_s[cb * 36 + k0 + ql]);
                uint32_t b1 = fu(qm_s[cb * 36 + k0 + 4 + ql]);
                mma8(e[0][ni], A[0][0], A[0][1], A[0][2], A[0][3], b0, b1);
                mma8(e[1][ni], A[1][0], A[1][1], A[1][2], A[1][3], b0, b1);
            }
        }

        // ---- p = ex2(e)*rsinv; csum; pT[m][n] ----
#pragma unroll
        for (int mi = 0; mi < 2; ++mi) {
            int r = row0 + mi * 16 + qr;
            float ri0 = rsinv_s[r], ri1 = rsinv_s[r + 8];
#pragma unroll
            for (int ni = 0; ni < 4; ++ni) {
                int col = col0 + ni * 8 + 2 * ql;
                float p00 = ex2f(e[mi][ni][0]) * ri0;
                float p01 = ex2f(e[mi][ni][1]) * ri0;
                float p10 = ex2f(e[mi][ni][2]) * ri1;
                float p11 = ex2f(e[mi][ni][3]) * ri1;
                csum[ni * 2]     += p00 + p10;
                csum[ni * 2 + 1] += p01 + p11;
                pT[col * 132 + r]           = to_tf32(p00);
                pT[(col + 1) * 132 + r]     = to_tf32(p01);
                pT[col * 132 + r + 8]       = to_tf32(p10);
                pT[(col + 1) * 132 + r + 8] = to_tf32(p11);
            }
        }
        CPA_WAIT(0);                 // vs(nt) ready
        __syncthreads();             // pT visible; qn reads done

        if (nt + 1 < NN / NT) {      // prefetch qn(nt+1) during Y-mma
#pragma unroll
            for (int k = 0; k < 2; ++k) {
                int idx4 = tid + k * 512;
                int r = idx4 >> 3, d4 = (idx4 & 7) << 2;
                cpa16(qn_u + (r * 36 + d4) * 4,
                      &g_qs[((size_t)b * NN + nb + NT + r) * DD + d4]);
            }
            CPA_COMMIT();
        }

        // ---- Y += v @ p ----
#pragma unroll
        for (int ks = 0; ks < 16; ++ks) {
            const int k0 = ks * 8;
            uint32_t A[2][4];
#pragma unroll
            for (int mi = 0; mi < 2; ++mi) {
                int r = row0 + mi * 16 + qr;
                A[mi][0] = fu(vs[r * 132 + k0 + ql]);
                A[mi][1] = fu(vs[(r + 8) * 132 + k0 + ql]);
                A[mi][2] = fu(vs[r * 132 + k0 + 4 + ql]);
                A[mi][3] = fu(vs[(r + 8) * 132 + k0 + 4 + ql]);
            }
#pragma unroll
            for (int ni = 0; ni < 4; ++ni) {
                int cb = col0 + ni * 8 + qr;
                uint32_t b0 = fu(pT[cb * 132 + k0 + ql]);
                uint32_t b1 = fu(pT[cb * 132 + k0 + 4 + ql]);
                mma8(yacc[0][ni], A[0][0], A[0][1], A[0][2], A[0][3], b0, b1);
                mma8(yacc[1][ni], A[1][0], A[1][1], A[1][2], A[1][3], b0, b1);
            }
        }
        __syncthreads();             // vs/pT reads done
        if (nt + 1 < NN / NT) {      // prefetch vs(nt+1) during next E+exp
#pragma unroll
            for (int k = 0; k < 8; ++k) {
                int idx4 = tid + k * 512;
                int c = idx4 >> 5, n4 = (idx4 & 31) << 2;
                cpa16(vs_u + (c * 132 + n4) * 4,
                      &g_v[((size_t)b * CC + c) * NN + nb + NT + n4]);
            }
            CPA_COMMIT();
        }
    }

    // ---------------- epilogue ----------------
#pragma unroll
    for (int i = 0; i < 8; ++i) {
        float v = csum[i];
        v += __shfl_xor_sync(0xffffffffu, v, 4);
        v += __shfl_xor_sync(0xffffffffu, v, 8);
        v += __shfl_xor_sync(0xffffffffu, v, 16);
        if (qr == 0) atomicAdd(&csum_s[col0 + (i >> 1) * 8 + 2 * ql + (i & 1)], v);
    }
    __syncthreads();
    if (tid < 128) cinv_s[tid] = 1.0f / (1e-9f + csum_s[tid]);
    for (int i = tid; i < CC * CC; i += 512) {
        int co = i >> 7, ci = i & 127;
        vs[co * 132 + ci] = to_tf32(wt[i]);
    }
    __syncthreads();

    // xm[c][m] = x - Y*cinv  -> pT[m][c]
    const float* xb = x + ((size_t)b * CC) * NN + m0;
#pragma unroll
    for (int mi = 0; mi < 2; ++mi) {
        int r = row0 + mi * 16 + qr;
#pragma unroll
        for (int ni = 0; ni < 4; ++ni) {
            int col = col0 + ni * 8 + 2 * ql;
            float2 x0 = __ldg((const float2*)&xb[(size_t)r * NN + col]);
            float2 x1 = __ldg((const float2*)&xb[(size_t)(r + 8) * NN + col]);
            float ci0 = cinv_s[col], ci1 = cinv_s[col + 1];
            pT[col * 132 + r]           = to_tf32(x0.x - yacc[mi][ni][0] * ci0);
            pT[(col + 1) * 132 + r]     = to_tf32(x0.y - yacc[mi][ni][1] * ci1);
            pT[col * 132 + r + 8]       = to_tf32(x1.x - yacc[mi][ni][2] * ci0);
            pT[(col + 1) * 132 + r + 8] = to_tf32(x1.y - yacc[mi][ni][3] * ci1);
        }
    }
    __syncthreads();

    // t = wt @ xm
    float tacc[2][4][4] = {};
#pragma unroll
    for (int ks = 0; ks < 16; ++ks) {
        const int k0 = ks * 8;
        uint32_t A[2][4];
#pragma unroll
        for (int mi = 0; mi < 2; ++mi) {
            int r = row0 + mi * 16 + qr;
            A[mi][0] = fu(vs[r * 132 + k0 + ql]);
            A[mi][1] = fu(vs[(r + 8) * 132 + k0 + ql]);
            A[mi][2] = fu(vs[r * 132 + k0 + 4 + ql]);
            A[mi][3] = fu(vs[(r + 8) * 132 + k0 + 4 + ql]);
        }
#pragma unroll
        for (int ni = 0; ni < 4; ++ni) {
            int cb = col0 + ni * 8 + qr;
            uint32_t b0 = fu(pT[cb * 132 + k0 + ql]);
            uint32_t b1 = fu(pT[cb * 132 + k0 + 4 + ql]);
            mma8(tacc[0][ni], A[0][0], A[0][1], A[0][2], A[0][3], b0, b1);
            mma8(tacc[1][ni], A[1][0], A[1][1], A[1][2], A[1][3], b0, b1);
        }
    }

    // out = x + relu(t*A + S)
#pragma unroll
    for (int mi = 0; mi < 2; ++mi) {
        int r = row0 + mi * 16 + qr;
        float a0 = A_s[r], s0 = S_s[r];
        float a1 = A_s[r + 8], s1 = S_s[r + 8];
#pragma unroll
        for (int ni = 0; ni < 4; ++ni) {
            int col = col0 + ni * 8 + 2 * ql;
            float2 x0 = __ldg((const float2*)&xb[(size_t)r * NN + col]);
            float2 x1 = __ldg((const float2*)&xb[(size_t)(r + 8) * NN + col]);
            float2 o0, o1;
            o0.x = x0.x + fmaxf(fmaf(tacc[mi][ni][0], a0, s0), 0.f);
            o0.y = x0.y + fmaxf(fmaf(tacc[mi][ni][1], a0, s0), 0.f);
            o1.x = x1.x + fmaxf(fmaf(tacc[mi][ni][2], a1, s1), 0.f);
            o1.y = x1.y + fmaxf(fmaf(tacc[mi][ni][3], a1, s1), 0.f);
            *(float2*)&out[((size_t)b * CC + r) * NN + m0 + col]     = o0;
            *(float2*)&out[((size_t)b * CC + r + 8) * NN + m0 + col] = o1;
        }
    }
}

// ======================================================================
extern "C" void kernel_launch(void* const* d_in, const int* in_sizes, int n_in,
                              void* d_out, int out_size) {
    const float* x     = (const float*)d_in[0];
    const float* wq    = (const float*)d_in[1];
    const float* wv    = (const float*)d_in[2];
    const float* bv    = (const float*)d_in[3];
    const float* wt    = (const float*)d_in[4];
    const float* bt    = (const float*)d_in[5];
    const float* gamma = (const float*)d_in[6];
    const float* beta  = (const float*)d_in[7];
    const float* mean  = (const float*)d_in[8];
    const float* var   = (const float*)d_in[9];
    float* out = (float*)d_out;

    const int S1 = (16896 + 21120 + 4128 + 128) * 4;   // 169088
    const int S2 = (128 + 3 * 4608) * 4;               // 55808
    const int S3 = (640 + 2 * 4608 + 2 * 16896) * 4;   // 174592

    cudaFuncSetAttribute(k_qv,     cudaFuncAttributeMaxDynamicSharedMemorySize, S1);
    cudaFuncSetAttribute(k_rowsum, cudaFuncAttributeMaxDynamicSharedMemorySize, S2);
    cudaFuncSetAttribute(k_attn,   cudaFuncAttributeMaxDynamicSharedMemorySize, S3);

    dim3 grid(NN / NT, BB);
    k_qv<<<grid, 320, S1>>>(x, wq, wv, bv);
    k_rowsum<<<grid, 512, S2>>>();
    k_attn<<<grid, 512, S3>>>(x, wt, bt, gamma, beta, mean, var, out);
}